// round 3
// baseline (speedup 1.0000x reference)
#include <cuda_runtime.h>
#include <cuda_bf16.h>
#include <cstdint>

// SpMM (COO, rows sorted): out[r,:] = sum_{e: rows[e]==r} vals[e] * embeds[cols[e],:]
// N=50000, E=800000, D=64, fp32. rows/cols are int32 (JAX default x64-disabled).
//
// R3: instruction-bound (issue 37%, L1 40%, L2 32%, DRAM 16%) -> raise work
// per instruction:
//  - float4 gather: 16 lanes x 16B = one 256B embed row
//  - 2 edges in flight per warp iteration (half-warp 0 = even edges,
//    half-warp 1 = odd edges), each half does register segmented reduction
//    over its (still sorted) subsequence, atomic flush at row boundaries
//  - zero via cudaMemsetAsync (graph memset node) instead of a kernel

#define D_FEAT        64
#define E_PER_WARP    128
#define WARPS_PER_CTA 8
#define CTA_THREADS   (WARPS_PER_CTA * 32)

__global__ __launch_bounds__(CTA_THREADS)
void spmm_kernel(const int*   __restrict__ rows,
                 const int*   __restrict__ cols,
                 const float* __restrict__ vals,
                 const float* __restrict__ embeds,
                 float*       __restrict__ out,
                 int n_edges)
{
    __shared__ int   s_row[WARPS_PER_CTA][E_PER_WARP];
    __shared__ int   s_col[WARPS_PER_CTA][E_PER_WARP];
    __shared__ float s_val[WARPS_PER_CTA][E_PER_WARP];

    const int warp = threadIdx.x >> 5;
    const int lane = threadIdx.x & 31;

    const int base = (blockIdx.x * WARPS_PER_CTA + warp) * E_PER_WARP;
    if (base >= n_edges) return;
    const int n = min(E_PER_WARP, n_edges - base);

    // Coalesced staging of edge metadata (broadcast LDS reads later).
    for (int i = lane; i < n; i += 32) {
        s_row[warp][i] = rows[base + i];
        s_col[warp][i] = cols[base + i];
        s_val[warp][i] = vals[base + i];
    }
    __syncwarp();

    const float4* __restrict__ emb4 = (const float4*)embeds;

    const int half = lane >> 4;        // 0: even edges, 1: odd edges
    const int fl   = lane & 15;        // feature slice: floats [4fl, 4fl+3]

    float4 acc = make_float4(0.f, 0.f, 0.f, 0.f);
    int cur_row = s_row[warp][half < n ? half : 0];

    #pragma unroll 4
    for (int i = half; i < n; i += 2) {
        const int r = s_row[warp][i];             // uniform per half-warp
        if (r != cur_row) {                       // rare (~8 rows / chunk)
            float* o = &out[cur_row * D_FEAT + 4 * fl];
            atomicAdd(o + 0, acc.x);
            atomicAdd(o + 1, acc.y);
            atomicAdd(o + 2, acc.z);
            atomicAdd(o + 3, acc.w);
            acc = make_float4(0.f, 0.f, 0.f, 0.f);
            cur_row = r;
        }
        const float  v = s_val[warp][i];
        const float4 e = emb4[s_col[warp][i] * (D_FEAT / 4) + fl];
        acc.x = fmaf(v, e.x, acc.x);
        acc.y = fmaf(v, e.y, acc.y);
        acc.z = fmaf(v, e.z, acc.z);
        acc.w = fmaf(v, e.w, acc.w);
    }
    {
        float* o = &out[cur_row * D_FEAT + 4 * fl];
        atomicAdd(o + 0, acc.x);
        atomicAdd(o + 1, acc.y);
        atomicAdd(o + 2, acc.z);
        atomicAdd(o + 3, acc.w);
    }
}

extern "C" void kernel_launch(void* const* d_in, const int* in_sizes, int n_in,
                              void* d_out, int out_size)
{
    const int*   rows   = (const int*)d_in[0];
    const int*   cols   = (const int*)d_in[1];
    const float* vals   = (const float*)d_in[2];
    const float* embeds = (const float*)d_in[3];
    float*       out    = (float*)d_out;

    const int n_edges = in_sizes[0];

    // zero the poisoned output (graph-capturable memset node)
    cudaMemsetAsync(out, 0, (size_t)out_size * sizeof(float));

    const int n_warp_chunks = (n_edges + E_PER_WARP - 1) / E_PER_WARP;
    const int blocks = (n_warp_chunks + WARPS_PER_CTA - 1) / WARPS_PER_CTA;
    spmm_kernel<<<blocks, CTA_THREADS>>>(rows, cols, vals, embeds, out, n_edges);
}

// round 5
// speedup vs baseline: 1.2229x; 1.2229x over previous
#include <cuda_runtime.h>
#include <cuda_bf16.h>
#include <cstdint>

// SpMM (COO, rows sorted): out[r,:] = sum_{e: rows[e]==r} vals[e] * embeds[cols[e],:]
// N=50000, E=800000, D=64, fp32. rows/cols int32.
//
// R4: previous versions were latency-exposed (6.2k long-running warps, serial
// 128-edge chains, nothing saturated). CSR warp-per-row:
//   1) build row_ptr from sorted rows (boundary detection, device scratch)
//   2) one warp per output row: lane = float2 feature slice, cols/vals
//      distributed via shfl, independent gathers (unroll-4 MLP), single
//      coalesced STG.64 -> no atomics, no memset, 50k warps for latency hiding.

#define D_FEAT    64
#define MAX_NODES 65537

__device__ int g_row_ptr[MAX_NODES + 1];

__global__ void build_row_ptr(const int* __restrict__ rows, int n_edges,
                              int n_nodes) {
    int e = blockIdx.x * blockDim.x + threadIdx.x;
    int stride = gridDim.x * blockDim.x;
    for (; e < n_edges; e += stride) {
        const int r    = rows[e];
        const int prev = (e == 0) ? -1 : rows[e - 1];
        for (int q = prev + 1; q <= r; q++) g_row_ptr[q] = e;       // N+1 total
        if (e == n_edges - 1)
            for (int q = r + 1; q <= n_nodes; q++) g_row_ptr[q] = n_edges;
    }
}

__global__ __launch_bounds__(256)
void spmm_csr(const int*   __restrict__ cols,
              const float* __restrict__ vals,
              const float* __restrict__ embeds,
              float*       __restrict__ out,
              int n_nodes)
{
    const int warp = (blockIdx.x * blockDim.x + threadIdx.x) >> 5;
    const int lane = threadIdx.x & 31;
    if (warp >= n_nodes) return;

    const int start = g_row_ptr[warp];
    const int end   = g_row_ptr[warp + 1];

    const float2* __restrict__ emb2 = (const float2*)embeds;
    float2 acc = make_float2(0.f, 0.f);

    for (int e0 = start; e0 < end; e0 += 32) {
        const int nb = min(32, end - e0);
        int   c = 0;
        float v = 0.0f;
        if (lane < nb) {
            c = cols[e0 + lane];
            v = vals[e0 + lane];
        }
        #pragma unroll 4
        for (int k = 0; k < nb; k++) {
            const int   cc = __shfl_sync(0xFFFFFFFFu, c, k);
            const float vv = __shfl_sync(0xFFFFFFFFu, v, k);
            const float2 t = emb2[cc * (D_FEAT / 2) + lane];
            acc.x = fmaf(vv, t.x, acc.x);
            acc.y = fmaf(vv, t.y, acc.y);
        }
    }
    // covers every row, including empty ones (acc = 0) -> no memset needed
    ((float2*)out)[warp * (D_FEAT / 2) + lane] = acc;
}

extern "C" void kernel_launch(void* const* d_in, const int* in_sizes, int n_in,
                              void* d_out, int out_size)
{
    const int*   rows   = (const int*)d_in[0];
    const int*   cols   = (const int*)d_in[1];
    const float* vals   = (const float*)d_in[2];
    const float* embeds = (const float*)d_in[3];
    float*       out    = (float*)d_out;

    const int n_edges = in_sizes[0];
    const int n_nodes = out_size / D_FEAT;

    build_row_ptr<<<592, 256>>>(rows, n_edges, n_nodes);

    const int warps  = n_nodes;                   // one warp per row
    const int blocks = (warps * 32 + 255) / 256;
    spmm_csr<<<blocks, 256>>>(cols, vals, embeds, out, n_nodes);
}

// round 6
// speedup vs baseline: 1.3316x; 1.0889x over previous
#include <cuda_runtime.h>
#include <cuda_bf16.h>
#include <cstdint>

// SpMM (COO, rows sorted): out[r,:] = sum_{e: rows[e]==r} vals[e] * embeds[cols[e],:]
// N=50000, E=800000, D=64, fp32. rows/cols int32.
//
// R5: R4's inner loop had 2 SHFLs (lat ~26 each) on the gather address chain.
// Replace with a packed (col,val) float2 scratch built in the row_ptr pass;
// spmm reads edge metadata via uniform broadcast LDG.64 (1 wavefront, L1-hit
// for 16 consecutive edges per 128B line). Inner loop: uniform LDG + gather
// LDG + 2 FFMA, unroll 4, acc-only dependence.

#define D_FEAT    64
#define MAX_NODES 65537
#define MAX_EDGES (1 << 20)

__device__ int    g_row_ptr[MAX_NODES + 1];
__device__ float2 g_edges[MAX_EDGES];          // (.x = bitcast col, .y = val)

__global__ void build_pack(const int*   __restrict__ rows,
                           const int*   __restrict__ cols,
                           const float* __restrict__ vals,
                           int n_edges, int n_nodes)
{
    int e = blockIdx.x * blockDim.x + threadIdx.x;
    int stride = gridDim.x * blockDim.x;
    for (; e < n_edges; e += stride) {
        g_edges[e] = make_float2(__int_as_float(cols[e]), vals[e]);

        const int r    = rows[e];
        const int prev = (e == 0) ? -1 : rows[e - 1];
        for (int q = prev + 1; q <= r; q++) g_row_ptr[q] = e;     // N+1 total
        if (e == n_edges - 1)
            for (int q = r + 1; q <= n_nodes; q++) g_row_ptr[q] = n_edges;
    }
}

__global__ __launch_bounds__(256)
void spmm_csr(const float* __restrict__ embeds,
              float*       __restrict__ out,
              int n_nodes)
{
    const int warp = (blockIdx.x * blockDim.x + threadIdx.x) >> 5;
    const int lane = threadIdx.x & 31;
    if (warp >= n_nodes) return;

    const int start = g_row_ptr[warp];
    const int end   = g_row_ptr[warp + 1];

    const float2* __restrict__ emb2 = (const float2*)embeds;
    float2 acc = make_float2(0.f, 0.f);

    #pragma unroll 4
    for (int e = start; e < end; e++) {
        const float2 cv = g_edges[e];                 // uniform broadcast
        const int    c  = __float_as_int(cv.x);
        const float2 t  = emb2[c * (D_FEAT / 2) + lane];
        acc.x = fmaf(cv.y, t.x, acc.x);
        acc.y = fmaf(cv.y, t.y, acc.y);
    }
    // covers every row, including empty ones (acc = 0) -> no memset needed
    ((float2*)out)[warp * (D_FEAT / 2) + lane] = acc;
}

extern "C" void kernel_launch(void* const* d_in, const int* in_sizes, int n_in,
                              void* d_out, int out_size)
{
    const int*   rows   = (const int*)d_in[0];
    const int*   cols   = (const int*)d_in[1];
    const float* vals   = (const float*)d_in[2];
    const float* embeds = (const float*)d_in[3];
    float*       out    = (float*)d_out;

    const int n_edges = in_sizes[0];
    const int n_nodes = out_size / D_FEAT;

    build_pack<<<592, 256>>>(rows, cols, vals, n_edges, n_nodes);

    const int blocks = (n_nodes * 32 + 255) / 256;   // one warp per row
    spmm_csr<<<blocks, 256>>>(embeds, out, n_nodes);
}